// round 16
// baseline (speedup 1.0000x reference)
#include <cuda_runtime.h>
#include <cuda_bf16.h>

#define NMAX 100000
#define DIM  256
#define NEG_SLOPE 0.01f

// -------------------- scratch (device globals) --------------------
__device__ float BUF_B[(size_t)NMAX * DIM];  // h_lin / h2_lin (gemm outputs)
__device__ float BUF_C[(size_t)NMAX * DIM];  // agg1
__device__ float BUF_D[(size_t)NMAX * DIM];  // agg2
__device__ float RA2[128 * DIM];             // leaky(features[root])
__device__ float RA3[128 * DIM];             // agg1[root]+b1
__device__ float RC2[128 * DIM];             // RA2 @ W2bot
__device__ float RC3[128 * DIM];             // RA3 @ Wlbot

__device__ __forceinline__ float leaky1(float v) { return v >= 0.0f ? v : NEG_SLOPE * v; }
__device__ __forceinline__ float4 leaky4(float4 v) {
    v.x = leaky1(v.x); v.y = leaky1(v.y); v.z = leaky1(v.z); v.w = leaky1(v.w);
    return v;
}
__device__ __forceinline__ float tf32r(float x) {
    float r; asm("cvt.rna.tf32.f32 %0, %1;" : "=f"(r) : "f"(x)); return r;
}

// -------------------- tf32 tensor-core GEMM (R10 config) --------------------
// Grid x-axis layout: [main rowtiles][2 aux blocks (opt)][zero blocks (opt)],
// grid.y = column tile (0/1).
// Main : C[nrows,256] = op(A)[nrows,256] @ B[256,256]
//        op = leaky(x + abias) if abias; epilogue +bias, +rc[batch[r]], leaky.
// Aux  : tiny root GEMM  auxC[auxRows,256] = auxA @ auxB (plain).
// Zero : grid-stride float4 zeroing of z0 then z1 (zN4 float4 each).
#define GAPAD 20   // As row pitch (16 + 4)
#define GBPAD 132  // Bs row pitch (128 + 4)
#define ZBLK 100   // zero-task blocks per grid.y column

__device__ __forceinline__ void mma8(float* c, const float* a, const float* b) {
    asm volatile(
        "mma.sync.aligned.m16n8k8.row.col.f32.tf32.tf32.f32 "
        "{%0,%1,%2,%3}, {%4,%5,%6,%7}, {%8,%9}, {%0,%1,%2,%3};"
        : "+f"(c[0]), "+f"(c[1]), "+f"(c[2]), "+f"(c[3])
        : "r"(__float_as_uint(a[0])), "r"(__float_as_uint(a[1])),
          "r"(__float_as_uint(a[2])), "r"(__float_as_uint(a[3])),
          "r"(__float_as_uint(b[0])), "r"(__float_as_uint(b[1])));
}

__global__ void __launch_bounds__(256, 3) gemm_tf32(
    const float* __restrict__ A, const float* __restrict__ Bmat,
    float* __restrict__ C, const float* __restrict__ bias,
    const float* __restrict__ rc, const int* __restrict__ batch,
    const float* __restrict__ abias, int nrows, int leakyFlag,
    const float* __restrict__ auxA, const float* __restrict__ auxB,
    float* __restrict__ auxC, int auxRows,
    float* __restrict__ z0, float* __restrict__ z1, long long zN4)
{
    __shared__ float As[2][64 * GAPAD];
    __shared__ float Bs[2][16 * GBPAD];

    const int bx = blockIdx.x;
    const int auxCnt  = auxA ? 2 : 0;
    const int zeroCnt = z0 ? ZBLK : 0;
    const int mainBlocks = gridDim.x - auxCnt - zeroCnt;

    // ---- zero task ----
    if (z0 && bx >= mainBlocks + auxCnt) {
        int zi = bx - mainBlocks - auxCnt;                       // 0..ZBLK-1
        long long tidg = ((long long)blockIdx.y * ZBLK + zi) * 256 + threadIdx.x;
        long long stride = (long long)ZBLK * gridDim.y * 256;
        float4 zv = make_float4(0.f, 0.f, 0.f, 0.f);
        for (long long i = tidg; i < 2 * zN4; i += stride) {
            if (i < zN4) ((float4*)z0)[i] = zv;
            else         ((float4*)z1)[i - zN4] = zv;
        }
        return;
    }

    int row0;
    if (auxA && bx >= mainBlocks) {
        A = auxA; Bmat = auxB; C = auxC;
        nrows = auxRows;
        bias = nullptr; rc = nullptr; abias = nullptr; leakyFlag = 0;
        row0 = (bx - mainBlocks) * 64;
    } else {
        row0 = bx * 64;
    }
    const int col0 = blockIdx.y * 128;

    const int tid = threadIdx.x;
    const int warp = tid >> 5, lane = tid & 31;
    const int g = lane >> 2, t = lane & 3;
    const int wm = (warp & 1) * 32;        // 0 / 32
    const int wn = (warp >> 1) * 32;       // 0,32,64,96

    float acc[2][4][4];
    #pragma unroll
    for (int mt = 0; mt < 2; mt++)
        #pragma unroll
        for (int nt = 0; nt < 4; nt++)
            #pragma unroll
            for (int i = 0; i < 4; i++) acc[mt][nt][i] = 0.0f;

    // staging thread coordinates
    const int ar  = tid >> 2;          // A row 0..63
    const int ac4 = (tid & 3) * 4;     // A k-col group
    const int kr0 = tid >> 5;          // B k-row 0..7
    const int kr1 = kr0 + 8;           // B k-row 8..15
    const int bc  = (tid & 31) * 4;    // B col group

    float4 ra, rb0, rb1;
    {
        int gr = row0 + ar;
        ra  = (gr < nrows) ? *(const float4*)(A + (long long)gr * 256 + ac4)
                           : make_float4(0.f, 0.f, 0.f, 0.f);
        rb0 = *(const float4*)(Bmat + (long long)kr0 * 256 + col0 + bc);
        rb1 = *(const float4*)(Bmat + (long long)kr1 * 256 + col0 + bc);
    }

    for (int ch = 0; ch < 16; ch++) {
        const int s = ch & 1;
        // ---- store current chunk into stage s (fused A transform + tf32) ----
        {
            float4 v = ra;
            if (abias) {
                float4 ab = *(const float4*)(abias + ch * 16 + ac4);
                v.x += ab.x; v.y += ab.y; v.z += ab.z; v.w += ab.w;
                v = leaky4(v);
            }
            float* ap = &As[s][ar * GAPAD + ac4];
            ap[0] = tf32r(v.x); ap[1] = tf32r(v.y);
            ap[2] = tf32r(v.z); ap[3] = tf32r(v.w);
            float4 w0, w1;
            w0.x = tf32r(rb0.x); w0.y = tf32r(rb0.y); w0.z = tf32r(rb0.z); w0.w = tf32r(rb0.w);
            w1.x = tf32r(rb1.x); w1.y = tf32r(rb1.y); w1.z = tf32r(rb1.z); w1.w = tf32r(rb1.w);
            *(float4*)&Bs[s][kr0 * GBPAD + bc] = w0;
            *(float4*)&Bs[s][kr1 * GBPAD + bc] = w1;
        }
        // ---- prefetch next chunk (latency hidden under barrier + compute) ----
        if (ch < 15) {
            int kn = ch * 16 + 16;
            int gr = row0 + ar;
            ra  = (gr < nrows) ? *(const float4*)(A + (long long)gr * 256 + kn + ac4)
                               : make_float4(0.f, 0.f, 0.f, 0.f);
            rb0 = *(const float4*)(Bmat + (long long)(kn + kr0) * 256 + col0 + bc);
            rb1 = *(const float4*)(Bmat + (long long)(kn + kr1) * 256 + col0 + bc);
        }
        __syncthreads();

        // ---- compute from stage s: 2 k8 substeps ----
        #pragma unroll
        for (int ks = 0; ks < 2; ks++) {
            int kk = ks * 8;
            float ah[2][4];
            #pragma unroll
            for (int mt = 0; mt < 2; mt++) {
                int base  = (wm + mt * 16 + g) * GAPAD + kk + t;
                int base8 = base + 8 * GAPAD;
                ah[mt][0] = As[s][base];     ah[mt][1] = As[s][base8];
                ah[mt][2] = As[s][base + 4]; ah[mt][3] = As[s][base8 + 4];
            }
            float bh[4][2];
            #pragma unroll
            for (int nt = 0; nt < 4; nt++) {
                int cb = wn + nt * 8 + g;
                bh[nt][0] = Bs[s][(kk + t) * GBPAD + cb];
                bh[nt][1] = Bs[s][(kk + t + 4) * GBPAD + cb];
            }
            #pragma unroll
            for (int mt = 0; mt < 2; mt++)
                #pragma unroll
                for (int nt = 0; nt < 4; nt++)
                    mma8(acc[mt][nt], ah[mt], bh[nt]);
        }
    }

    // ---- epilogue ----
    #pragma unroll
    for (int mt = 0; mt < 2; mt++) {
        int r_lo = row0 + wm + mt * 16 + g;
        #pragma unroll
        for (int h = 0; h < 2; h++) {
            int gr = r_lo + 8 * h;
            if (gr >= nrows) continue;
            const float* rcrow = rc ? rc + (long long)batch[gr] * 256 : nullptr;
            #pragma unroll
            for (int nt = 0; nt < 4; nt++) {
                int gc = col0 + wn + nt * 8 + 2 * t;
                float vx = acc[mt][nt][h * 2 + 0];
                float vy = acc[mt][nt][h * 2 + 1];
                if (bias) { float2 bb = *(const float2*)(bias + gc); vx += bb.x; vy += bb.y; }
                if (rcrow) { float2 rr = *(const float2*)(rcrow + gc); vx += rr.x; vy += rr.y; }
                if (leakyFlag) { vx = leaky1(vx); vy = leaky1(vy); }
                float2 o; o.x = vx; o.y = vy;
                *(float2*)(C + (long long)gr * 256 + gc) = o;
            }
        }
    }
}

// -------------------- edge scatter, column-half pass --------------------
// agg[dst][colOff:colOff+128] += w * h[src][colOff:colOff+128]
// One warp per edge, one float4 + one RED.v4 per lane. Two passes per
// scatter keep the per-pass h/agg working set (~100 MB) inside L2.
__global__ void __launch_bounds__(256) scatter_kernel(
    const float* __restrict__ h, float* __restrict__ agg,
    const int* __restrict__ src, const int* __restrict__ dst,
    const float* __restrict__ w, int E, int colOff)
{
    int warp = (blockIdx.x * blockDim.x + threadIdx.x) >> 5;
    int lane = threadIdx.x & 31;
    if (warp >= E) return;
    int s = src[warp], d = dst[warp];
    float wt = w[warp];
    const float4* hrow = (const float4*)(h + (long long)s * DIM + colOff);
    float* p = agg + (long long)d * DIM + colOff + lane * 4;
    float4 v = __ldg(hrow + lane);
    asm volatile("red.global.add.v4.f32 [%0], {%1,%2,%3,%4};"
                 :: "l"(p), "f"(wt * v.x), "f"(wt * v.y), "f"(wt * v.z), "f"(wt * v.w)
                 : "memory");
}

// -------------------- small helpers --------------------
// dst[b] = op(src[root_idx[b]]) ; op: +abias (optional), leaky (optional)
__global__ void __launch_bounds__(64) gather_root(
    const float* __restrict__ src, const int* __restrict__ root_idx,
    const float* __restrict__ abias,
    float* __restrict__ dst, int applyLeaky)
{
    int b = blockIdx.x, t = threadIdx.x;
    int r = root_idx[b];
    float4 v = ((const float4*)(src + (long long)r * DIM))[t];
    if (abias) {
        float4 ab = ((const float4*)abias)[t];
        v.x += ab.x; v.y += ab.y; v.z += ab.z; v.w += ab.w;
    }
    if (applyLeaky) v = leaky4(v);
    ((float4*)(dst + (long long)b * DIM))[t] = v;
}

// -------------------- launch --------------------
extern "C" void kernel_launch(void* const* d_in, const int* in_sizes, int n_in,
                              void* d_out, int out_size)
{
    const float* features = (const float*)d_in[0];
    const float* values   = (const float*)d_in[1];
    const float* W1       = (const float*)d_in[2];
    const float* b1       = (const float*)d_in[3];
    const float* W2       = (const float*)d_in[4];
    const float* b2       = (const float*)d_in[5];
    const float* Wl       = (const float*)d_in[6];
    const float* bl       = (const float*)d_in[7];
    const int*   adjs     = (const int*)d_in[8];
    const int*   batch    = (const int*)d_in[9];
    const int*   root_idx = (const int*)d_in[10];
    float* out = (float*)d_out;

    const int N = in_sizes[0] / DIM;
    const int E = in_sizes[1];
    const int B = in_sizes[10];
    const int* src = adjs;
    const int* dst = adjs + E;

    float *bufB, *bufC, *bufD, *ra2, *ra3, *rc2, *rc3;
    cudaGetSymbolAddress((void**)&bufB, BUF_B);
    cudaGetSymbolAddress((void**)&bufC, BUF_C);
    cudaGetSymbolAddress((void**)&bufD, BUF_D);
    cudaGetSymbolAddress((void**)&ra2, RA2);
    cudaGetSymbolAddress((void**)&ra3, RA3);
    cudaGetSymbolAddress((void**)&rc2, RC2);
    cudaGetSymbolAddress((void**)&rc3, RC3);

    int mainBlocks = (N + 63) / 64;
    dim3 grid1(mainBlocks + 2 + ZBLK, 2);   // main + aux(2) + zero(ZBLK)
    dim3 grid2(mainBlocks + 2, 2);          // main + aux(2)
    dim3 grid3(mainBlocks, 2);              // main only
    int scatterBlocks = (E + 7) / 8;
    long long n4 = (long long)N * DIM / 4;

    // 1. gather leaky(features[root])
    gather_root<<<B, 64>>>(features, root_idx, nullptr, ra2, 1);
    // 2. h_lin = features @ W1  [+ aux: rc2 = RA2 @ W2bot] [+ zero bufC,bufD]
    gemm_tf32<<<grid1, 256>>>(features, W1, bufB,
                              nullptr, nullptr, nullptr, nullptr, N, 0,
                              ra2, W2 + 65536, rc2, B,
                              bufC, bufD, n4);
    // 3. agg1[dst] += v * h_lin[src]   (two L2-resident column halves)
    scatter_kernel<<<scatterBlocks, 256>>>(bufB, bufC, src, dst, values, E, 0);
    scatter_kernel<<<scatterBlocks, 256>>>(bufB, bufC, src, dst, values, E, 128);
    // 4. ra3 = agg1[root] + b1
    gather_root<<<B, 64>>>(bufC, root_idx, b1, ra3, 0);
    // 5. h2_lin = leaky(agg1+b1) @ W2top + rc2[batch]  [+ aux: rc3 = RA3 @ Wlbot]
    gemm_tf32<<<grid2, 256>>>(bufC, W2, bufB,
                              nullptr, rc2, batch, b1, N, 0,
                              ra3, Wl + 65536, rc3, B,
                              nullptr, nullptr, 0);
    // 6. agg2[dst] += v * h2_lin[src]  (two L2-resident column halves)
    scatter_kernel<<<scatterBlocks, 256>>>(bufB, bufD, src, dst, values, E, 0);
    scatter_kernel<<<scatterBlocks, 256>>>(bufB, bufD, src, dst, values, E, 128);
    // 7. out = leaky( leaky(agg2+b2) @ Wltop + rc3[batch] + bl )
    gemm_tf32<<<grid3, 256>>>(bufD, Wl, out,
                              bl, rc3, batch, b2, N, 1,
                              nullptr, nullptr, nullptr, 0,
                              nullptr, nullptr, 0);
}

// round 17
// speedup vs baseline: 1.0605x; 1.0605x over previous
#include <cuda_runtime.h>
#include <cuda_bf16.h>

#define NMAX 100000
#define DIM  256
#define NEG_SLOPE 0.01f

// -------------------- scratch (device globals) --------------------
__device__ float BUF_B[(size_t)NMAX * DIM];  // h_lin / h2_lin (gemm outputs)
__device__ float BUF_C[(size_t)NMAX * DIM];  // agg1
__device__ float BUF_D[(size_t)NMAX * DIM];  // agg2
__device__ float RA2[128 * DIM];             // leaky(features[root])
__device__ float RA3[128 * DIM];             // agg1[root]+b1
__device__ float RC2[128 * DIM];             // RA2 @ W2bot
__device__ float RC3[128 * DIM];             // RA3 @ Wlbot

__device__ __forceinline__ float leaky1(float v) { return v >= 0.0f ? v : NEG_SLOPE * v; }
__device__ __forceinline__ float4 leaky4(float4 v) {
    v.x = leaky1(v.x); v.y = leaky1(v.y); v.z = leaky1(v.z); v.w = leaky1(v.w);
    return v;
}
__device__ __forceinline__ float tf32r(float x) {
    float r; asm("cvt.rna.tf32.f32 %0, %1;" : "=f"(r) : "f"(x)); return r;
}

// -------------------- tf32 tensor-core GEMM (R10 config) --------------------
// Grid x-axis layout: [main rowtiles][2 aux blocks (opt)][zero blocks (opt)],
// grid.y = column tile (0/1).
// Main : C[nrows,256] = op(A)[nrows,256] @ B[256,256]
//        op = leaky(x + abias) if abias; epilogue +bias, +rc[batch[r]], leaky.
// Aux  : tiny root GEMM  auxC[auxRows,256] = auxA @ auxB (plain).
// Zero : grid-stride float4 zeroing of z0 then z1 (zN4 float4 each).
#define GAPAD 20   // As row pitch (16 + 4)
#define GBPAD 132  // Bs row pitch (128 + 4)
#define ZBLK 100   // zero-task blocks per grid.y column

__device__ __forceinline__ void mma8(float* c, const float* a, const float* b) {
    asm volatile(
        "mma.sync.aligned.m16n8k8.row.col.f32.tf32.tf32.f32 "
        "{%0,%1,%2,%3}, {%4,%5,%6,%7}, {%8,%9}, {%0,%1,%2,%3};"
        : "+f"(c[0]), "+f"(c[1]), "+f"(c[2]), "+f"(c[3])
        : "r"(__float_as_uint(a[0])), "r"(__float_as_uint(a[1])),
          "r"(__float_as_uint(a[2])), "r"(__float_as_uint(a[3])),
          "r"(__float_as_uint(b[0])), "r"(__float_as_uint(b[1])));
}

__global__ void __launch_bounds__(256, 3) gemm_tf32(
    const float* __restrict__ A, const float* __restrict__ Bmat,
    float* __restrict__ C, const float* __restrict__ bias,
    const float* __restrict__ rc, const int* __restrict__ batch,
    const float* __restrict__ abias, int nrows, int leakyFlag,
    const float* __restrict__ auxA, const float* __restrict__ auxB,
    float* __restrict__ auxC, int auxRows,
    float* __restrict__ z0, float* __restrict__ z1, long long zN4)
{
    __shared__ float As[2][64 * GAPAD];
    __shared__ float Bs[2][16 * GBPAD];

    const int bx = blockIdx.x;
    const int auxCnt  = auxA ? 2 : 0;
    const int zeroCnt = z0 ? ZBLK : 0;
    const int mainBlocks = gridDim.x - auxCnt - zeroCnt;

    // ---- zero task ----
    if (z0 && bx >= mainBlocks + auxCnt) {
        int zi = bx - mainBlocks - auxCnt;                       // 0..ZBLK-1
        long long tidg = ((long long)blockIdx.y * ZBLK + zi) * 256 + threadIdx.x;
        long long stride = (long long)ZBLK * gridDim.y * 256;
        float4 zv = make_float4(0.f, 0.f, 0.f, 0.f);
        for (long long i = tidg; i < 2 * zN4; i += stride) {
            if (i < zN4) ((float4*)z0)[i] = zv;
            else         ((float4*)z1)[i - zN4] = zv;
        }
        return;
    }

    int row0;
    if (auxA && bx >= mainBlocks) {
        A = auxA; Bmat = auxB; C = auxC;
        nrows = auxRows;
        bias = nullptr; rc = nullptr; abias = nullptr; leakyFlag = 0;
        row0 = (bx - mainBlocks) * 64;
    } else {
        row0 = bx * 64;
    }
    const int col0 = blockIdx.y * 128;

    const int tid = threadIdx.x;
    const int warp = tid >> 5, lane = tid & 31;
    const int g = lane >> 2, t = lane & 3;
    const int wm = (warp & 1) * 32;        // 0 / 32
    const int wn = (warp >> 1) * 32;       // 0,32,64,96

    float acc[2][4][4];
    #pragma unroll
    for (int mt = 0; mt < 2; mt++)
        #pragma unroll
        for (int nt = 0; nt < 4; nt++)
            #pragma unroll
            for (int i = 0; i < 4; i++) acc[mt][nt][i] = 0.0f;

    // staging thread coordinates
    const int ar  = tid >> 2;          // A row 0..63
    const int ac4 = (tid & 3) * 4;     // A k-col group
    const int kr0 = tid >> 5;          // B k-row 0..7
    const int kr1 = kr0 + 8;           // B k-row 8..15
    const int bc  = (tid & 31) * 4;    // B col group

    float4 ra, rb0, rb1;
    {
        int gr = row0 + ar;
        ra  = (gr < nrows) ? *(const float4*)(A + (long long)gr * 256 + ac4)
                           : make_float4(0.f, 0.f, 0.f, 0.f);
        rb0 = *(const float4*)(Bmat + (long long)kr0 * 256 + col0 + bc);
        rb1 = *(const float4*)(Bmat + (long long)kr1 * 256 + col0 + bc);
    }

    for (int ch = 0; ch < 16; ch++) {
        const int s = ch & 1;
        // ---- store current chunk into stage s (fused A transform + tf32) ----
        {
            float4 v = ra;
            if (abias) {
                float4 ab = *(const float4*)(abias + ch * 16 + ac4);
                v.x += ab.x; v.y += ab.y; v.z += ab.z; v.w += ab.w;
                v = leaky4(v);
            }
            float* ap = &As[s][ar * GAPAD + ac4];
            ap[0] = tf32r(v.x); ap[1] = tf32r(v.y);
            ap[2] = tf32r(v.z); ap[3] = tf32r(v.w);
            float4 w0, w1;
            w0.x = tf32r(rb0.x); w0.y = tf32r(rb0.y); w0.z = tf32r(rb0.z); w0.w = tf32r(rb0.w);
            w1.x = tf32r(rb1.x); w1.y = tf32r(rb1.y); w1.z = tf32r(rb1.z); w1.w = tf32r(rb1.w);
            *(float4*)&Bs[s][kr0 * GBPAD + bc] = w0;
            *(float4*)&Bs[s][kr1 * GBPAD + bc] = w1;
        }
        // ---- prefetch next chunk (latency hidden under barrier + compute) ----
        if (ch < 15) {
            int kn = ch * 16 + 16;
            int gr = row0 + ar;
            ra  = (gr < nrows) ? *(const float4*)(A + (long long)gr * 256 + kn + ac4)
                               : make_float4(0.f, 0.f, 0.f, 0.f);
            rb0 = *(const float4*)(Bmat + (long long)(kn + kr0) * 256 + col0 + bc);
            rb1 = *(const float4*)(Bmat + (long long)(kn + kr1) * 256 + col0 + bc);
        }
        __syncthreads();

        // ---- compute from stage s: 2 k8 substeps ----
        #pragma unroll
        for (int ks = 0; ks < 2; ks++) {
            int kk = ks * 8;
            float ah[2][4];
            #pragma unroll
            for (int mt = 0; mt < 2; mt++) {
                int base  = (wm + mt * 16 + g) * GAPAD + kk + t;
                int base8 = base + 8 * GAPAD;
                ah[mt][0] = As[s][base];     ah[mt][1] = As[s][base8];
                ah[mt][2] = As[s][base + 4]; ah[mt][3] = As[s][base8 + 4];
            }
            float bh[4][2];
            #pragma unroll
            for (int nt = 0; nt < 4; nt++) {
                int cb = wn + nt * 8 + g;
                bh[nt][0] = Bs[s][(kk + t) * GBPAD + cb];
                bh[nt][1] = Bs[s][(kk + t + 4) * GBPAD + cb];
            }
            #pragma unroll
            for (int mt = 0; mt < 2; mt++)
                #pragma unroll
                for (int nt = 0; nt < 4; nt++)
                    mma8(acc[mt][nt], ah[mt], bh[nt]);
        }
    }

    // ---- epilogue ----
    #pragma unroll
    for (int mt = 0; mt < 2; mt++) {
        int r_lo = row0 + wm + mt * 16 + g;
        #pragma unroll
        for (int h = 0; h < 2; h++) {
            int gr = r_lo + 8 * h;
            if (gr >= nrows) continue;
            const float* rcrow = rc ? rc + (long long)batch[gr] * 256 : nullptr;
            #pragma unroll
            for (int nt = 0; nt < 4; nt++) {
                int gc = col0 + wn + nt * 8 + 2 * t;
                float vx = acc[mt][nt][h * 2 + 0];
                float vy = acc[mt][nt][h * 2 + 1];
                if (bias) { float2 bb = *(const float2*)(bias + gc); vx += bb.x; vy += bb.y; }
                if (rcrow) { float2 rr = *(const float2*)(rcrow + gc); vx += rr.x; vy += rr.y; }
                if (leakyFlag) { vx = leaky1(vx); vy = leaky1(vy); }
                float2 o; o.x = vx; o.y = vy;
                *(float2*)(C + (long long)gr * 256 + gc) = o;
            }
        }
    }
}

// -------------------- edge scatter, column-half pass, 4 edges/warp ----------
// agg[dst][colOff:+128] += w * h[src][colOff:+128] for 4 edges per warp.
// Independent index loads -> 4 concurrent gathers (MLP=4) -> 4 REDs.
__global__ void __launch_bounds__(256) scatter_kernel(
    const float* __restrict__ h, float* __restrict__ agg,
    const int* __restrict__ src, const int* __restrict__ dst,
    const float* __restrict__ w, int E, int colOff)
{
    int warp = (blockIdx.x * blockDim.x + threadIdx.x) >> 5;
    int lane = threadIdx.x & 31;
    int e0 = warp * 4;
    if (e0 >= E) return;

    int   dd[4];
    float wt[4];
    float4 v[4];
    #pragma unroll
    for (int j = 0; j < 4; j++) {
        int e = e0 + j;
        if (e < E) {
            int s = __ldg(src + e);
            dd[j] = __ldg(dst + e);
            wt[j] = __ldg(w + e);
            v[j] = __ldg((const float4*)(h + (long long)s * DIM + colOff) + lane);
        } else {
            dd[j] = -1;
        }
    }
    #pragma unroll
    for (int j = 0; j < 4; j++) {
        if (dd[j] < 0) continue;
        float* p = agg + (long long)dd[j] * DIM + colOff + lane * 4;
        asm volatile("red.global.add.v4.f32 [%0], {%1,%2,%3,%4};"
                     :: "l"(p), "f"(wt[j] * v[j].x), "f"(wt[j] * v[j].y),
                        "f"(wt[j] * v[j].z), "f"(wt[j] * v[j].w)
                     : "memory");
    }
}

// -------------------- small helpers --------------------
// dst[b] = op(src[root_idx[b]]) ; op: +abias (optional), leaky (optional)
__global__ void __launch_bounds__(64) gather_root(
    const float* __restrict__ src, const int* __restrict__ root_idx,
    const float* __restrict__ abias,
    float* __restrict__ dst, int applyLeaky)
{
    int b = blockIdx.x, t = threadIdx.x;
    int r = root_idx[b];
    float4 v = ((const float4*)(src + (long long)r * DIM))[t];
    if (abias) {
        float4 ab = ((const float4*)abias)[t];
        v.x += ab.x; v.y += ab.y; v.z += ab.z; v.w += ab.w;
    }
    if (applyLeaky) v = leaky4(v);
    ((float4*)(dst + (long long)b * DIM))[t] = v;
}

// -------------------- launch --------------------
extern "C" void kernel_launch(void* const* d_in, const int* in_sizes, int n_in,
                              void* d_out, int out_size)
{
    const float* features = (const float*)d_in[0];
    const float* values   = (const float*)d_in[1];
    const float* W1       = (const float*)d_in[2];
    const float* b1       = (const float*)d_in[3];
    const float* W2       = (const float*)d_in[4];
    const float* b2       = (const float*)d_in[5];
    const float* Wl       = (const float*)d_in[6];
    const float* bl       = (const float*)d_in[7];
    const int*   adjs     = (const int*)d_in[8];
    const int*   batch    = (const int*)d_in[9];
    const int*   root_idx = (const int*)d_in[10];
    float* out = (float*)d_out;

    const int N = in_sizes[0] / DIM;
    const int E = in_sizes[1];
    const int B = in_sizes[10];
    const int* src = adjs;
    const int* dst = adjs + E;

    float *bufB, *bufC, *bufD, *ra2, *ra3, *rc2, *rc3;
    cudaGetSymbolAddress((void**)&bufB, BUF_B);
    cudaGetSymbolAddress((void**)&bufC, BUF_C);
    cudaGetSymbolAddress((void**)&bufD, BUF_D);
    cudaGetSymbolAddress((void**)&ra2, RA2);
    cudaGetSymbolAddress((void**)&ra3, RA3);
    cudaGetSymbolAddress((void**)&rc2, RC2);
    cudaGetSymbolAddress((void**)&rc3, RC3);

    int mainBlocks = (N + 63) / 64;
    dim3 grid1(mainBlocks + 2 + ZBLK, 2);   // main + aux(2) + zero(ZBLK)
    dim3 grid2(mainBlocks + 2, 2);          // main + aux(2)
    dim3 grid3(mainBlocks, 2);              // main only
    int scatterBlocks = (E + 31) / 32;      // 8 warps x 4 edges per block
    long long n4 = (long long)N * DIM / 4;

    // 1. gather leaky(features[root])
    gather_root<<<B, 64>>>(features, root_idx, nullptr, ra2, 1);
    // 2. h_lin = features @ W1  [+ aux: rc2 = RA2 @ W2bot] [+ zero bufC,bufD]
    gemm_tf32<<<grid1, 256>>>(features, W1, bufB,
                              nullptr, nullptr, nullptr, nullptr, N, 0,
                              ra2, W2 + 65536, rc2, B,
                              bufC, bufD, n4);
    // 3. agg1[dst] += v * h_lin[src]   (two L2-resident column halves)
    scatter_kernel<<<scatterBlocks, 256>>>(bufB, bufC, src, dst, values, E, 0);
    scatter_kernel<<<scatterBlocks, 256>>>(bufB, bufC, src, dst, values, E, 128);
    // 4. ra3 = agg1[root] + b1
    gather_root<<<B, 64>>>(bufC, root_idx, b1, ra3, 0);
    // 5. h2_lin = leaky(agg1+b1) @ W2top + rc2[batch]  [+ aux: rc3 = RA3 @ Wlbot]
    gemm_tf32<<<grid2, 256>>>(bufC, W2, bufB,
                              nullptr, rc2, batch, b1, N, 0,
                              ra3, Wl + 65536, rc3, B,
                              nullptr, nullptr, 0);
    // 6. agg2[dst] += v * h2_lin[src]  (two L2-resident column halves)
    scatter_kernel<<<scatterBlocks, 256>>>(bufB, bufD, src, dst, values, E, 0);
    scatter_kernel<<<scatterBlocks, 256>>>(bufB, bufD, src, dst, values, E, 128);
    // 7. out = leaky( leaky(agg2+b2) @ Wltop + rc3[batch] + bl )
    gemm_tf32<<<grid3, 256>>>(bufD, Wl, out,
                              bl, rc3, batch, b2, N, 1,
                              nullptr, nullptr, nullptr, 0,
                              nullptr, nullptr, 0);
}